// round 6
// baseline (speedup 1.0000x reference)
#include <cuda_runtime.h>
#include <math.h>

#define N   384
#define NN  (384*384)
#define JH  192

// ---- scratch (device globals; no allocation allowed) ----
__device__ float g_q   [256*N];
__device__ float g_Kn  [256*N];
__device__ float g_Vn  [256*N];
__device__ float g_nf  [256*N];
__device__ float g_hEo [64*N];
__device__ float g_mask[N];

// ---- packed f32x2 helpers (Blackwell FFMA2) ----
__device__ __forceinline__ unsigned long long pk2(float a, float b) {
    unsigned long long d;
    asm("mov.b64 %0, {%1, %2};" : "=l"(d) : "f"(a), "f"(b));
    return d;
}
__device__ __forceinline__ unsigned long long fma2(unsigned long long a,
                                                   unsigned long long b,
                                                   unsigned long long c) {
    unsigned long long d;
    asm("fma.rn.f32x2 %0, %1, %2, %3;" : "=l"(d) : "l"(a), "l"(b), "l"(c));
    return d;
}
__device__ __forceinline__ float2 upk(unsigned long long v) {
    float2 r;
    asm("mov.b64 {%0, %1}, %2;" : "=f"(r.x), "=f"(r.y) : "l"(v));
    return r;
}
union F4U { float4 f; unsigned long long u[2]; };

// ---- cluster / DSMEM helpers ----
__device__ __forceinline__ unsigned smem_u32(const void* p) {
    unsigned a;
    asm("{ .reg .u64 t; cvta.to.shared.u64 t, %1; cvt.u32.u64 %0, t; }"
        : "=r"(a) : "l"(p));
    return a;
}
__device__ __forceinline__ unsigned mapa_rank(unsigned addr, unsigned rank) {
    unsigned r;
    asm("mapa.shared::cluster.u32 %0, %1, %2;" : "=r"(r) : "r"(addr), "r"(rank));
    return r;
}
__device__ __forceinline__ float ld_dsmem(unsigned addr) {
    float v;
    asm volatile("ld.shared::cluster.f32 %0, [%1];" : "=f"(v) : "r"(addr));
    return v;
}
#define CLUSTER_SYNC() do { \
    asm volatile("barrier.cluster.arrive.aligned;" ::: "memory"); \
    asm volatile("barrier.cluster.wait.aligned;"   ::: "memory"); \
} while (0)

// ============================================================
// Kernel 1: fused GEMM q|Kn|Vn. M=768, K=128, cols=384.
// grid(24,12), 256 thr, tile 32x32. Block(0,0) decodes mask.
// ============================================================
__global__ __launch_bounds__(256) void k_prep(
    const float* __restrict__ nodes,
    const float* __restrict__ Wq,
    const float* __restrict__ Wk,
    const float* __restrict__ Wv,
    const unsigned int* __restrict__ maskw)
{
    __shared__ float Ws[32][33];
    __shared__ float Ns[32][36];
    __shared__ int s_flagF, s_flagB;
    int tid = threadIdx.x;

    if (blockIdx.x == 0 && blockIdx.y == 0) {
        if (tid == 0) { s_flagF = 0; s_flagB = 0; }
        __syncthreads();
        if (tid < 96) {
            unsigned v = maskw[tid];
            if (v == 0x3f800000u) atomicOr(&s_flagF, 1);   // float32 1.0
            else if (v > 1u)      atomicOr(&s_flagB, 1);   // packed u8
        }
        __syncthreads();
        bool byte_mode = (!s_flagF) && s_flagB;
        for (int j = tid; j < N; j += 256) {
            float val;
            if (byte_mode) {
                unsigned w = maskw[j >> 2];
                val = ((w >> ((j & 3) * 8)) & 0xffu) ? 1.0f : 0.0f;
            } else {
                val = maskw[j] ? 1.0f : 0.0f;   // int32 or f32 bits
            }
            g_mask[j] = val;
        }
    }

    int r0 = blockIdx.x * 32, n0 = blockIdx.y * 32;
    int co = tid & 31, ro = (tid >> 5) * 4;
    float acc[4] = {0.f, 0.f, 0.f, 0.f};

    for (int k0 = 0; k0 < 128; k0 += 32) {
        {
            int rr = tid >> 3, kl = (tid & 7) * 4;
            int r = r0 + rr;
            const float* wp;
            if      (r < 256) wp = Wq + r * 128;
            else if (r < 512) wp = Wk + (r - 256) * 192;
            else              wp = Wv + (r - 512) * 192;
            float4 w = *(const float4*)(wp + k0 + kl);
            Ws[rr][kl+0] = w.x; Ws[rr][kl+1] = w.y;
            Ws[rr][kl+2] = w.z; Ws[rr][kl+3] = w.w;
        }
        {
            int kk = tid >> 3, cl = (tid & 7) * 4;
            float4 v = *(const float4*)(nodes + (k0 + kk) * N + n0 + cl);
            Ns[kk][cl+0] = v.x; Ns[kk][cl+1] = v.y;
            Ns[kk][cl+2] = v.z; Ns[kk][cl+3] = v.w;
        }
        __syncthreads();
        #pragma unroll
        for (int k = 0; k < 32; k++) {
            float ev = Ns[k][co];
            acc[0] = fmaf(Ws[ro+0][k], ev, acc[0]);
            acc[1] = fmaf(Ws[ro+1][k], ev, acc[1]);
            acc[2] = fmaf(Ws[ro+2][k], ev, acc[2]);
            acc[3] = fmaf(Ws[ro+3][k], ev, acc[3]);
        }
        __syncthreads();
    }
    #pragma unroll
    for (int q = 0; q < 4; q++) {
        int r = r0 + ro + q;
        float* op;
        if      (r < 256) op = g_q  + r * N;
        else if (r < 512) op = g_Kn + (r - 256) * N;
        else              op = g_Vn + (r - 512) * N;
        op[n0 + co] = acc[q];
    }
}

// ============================================================
// Kernel 2: clustered attention. 2 CTAs per row i (j-halves).
// grid(768) cluster(2), 384 thr, ~70KB dyn smem (2-3 CTAs/SM).
// ============================================================
#define ES_ST 196
#define ATTN_FLOATS (64*ES_ST + JH*12 + 3*256 + 512 + 512 + 512 + 16 + 8 + 8 + JH)
#define ATTN_SMEM (ATTN_FLOATS * 4)

__global__ __launch_bounds__(384, 3) __cluster_dims__(2, 1, 1)
void k_attn(
    const float* __restrict__ edges,
    const float* __restrict__ Wk,
    const float* __restrict__ Wv)
{
    extern __shared__ float sm[];
    float* Es    = sm;                    // [64][196]
    float* s_p   = Es + 64 * ES_ST;       // [192][12] raw exp values
    float* s_qi  = s_p + JH * 12;         // 256
    float* s_Kni = s_qi + 256;            // 256
    float* s_Vni = s_Kni + 256;           // 256
    float* s_Qk  = s_Vni + 256;           // [64][8]
    float* s_T   = s_Qk + 512;            // [8][64] scaled partial T (exchanged)
    float* s_Tp  = s_T + 512;             // peer's T copy
    float* s_ms  = s_Tp + 512;            // [16] m[8], s[8] (exchanged)
    float* s_fac = s_ms + 16;             // [8]
    float* s_sb  = s_fac + 8;             // [8]
    float* s_mf  = s_sb + 8;              // [192]

    int bx = blockIdx.x;
    int i = bx >> 1;
    unsigned rank = bx & 1;
    int jb = (int)rank * JH;
    int tid = threadIdx.x, lane = tid & 31, wid = tid >> 5;

    float maski = g_mask[i];

    if (tid < 256) {
        s_qi [tid] = g_q [tid * N + i];
        s_Kni[tid] = g_Kn[tid * N + i];
        s_Vni[tid] = g_Vn[tid * N + i];
    }
    if (tid < JH) s_mf[tid] = g_mask[jb + tid];

    // stage edges[e, i, jb..jb+191]: 64 x 48 float4 = 3072 / 384 thr = 8 each
    const float* erow = edges + (size_t)i * N + jb;
    #pragma unroll
    for (int k = 0; k < 8; k++) {
        int idx = k * 384 + tid;
        int e = idx / 48, c4 = idx - e * 48;
        float4 v = *(const float4*)(erow + (size_t)e * NN + c4 * 4);
        *(float4*)&Es[e * ES_ST + c4 * 4] = v;
    }
    __syncthreads();

    const float rs = 0.17677669529663687f;  // 1/sqrt(32)

    // Qk[e][h] = rs * sum_a q[h*32+a] * Wk[h*32+a][128+e]  (512 items)
    {
        int idx = tid;
        #pragma unroll
        for (int rep = 0; rep < 2; rep++) {
            if (idx < 512) {
                int h = idx >> 6, e = idx & 63;
                const float* wkp = Wk + (h * 32) * 192 + 128 + e;
                float acc = 0.f;
                #pragma unroll
                for (int a = 0; a < 32; a++) acc = fmaf(s_qi[h * 32 + a], wkp[a * 192], acc);
                s_Qk[e * 8 + h] = acc * rs;
            }
            idx += 384;
        }
    }
    if (tid < 256) {   // sim_base[h], warps 0..7
        float v = s_qi[tid] * s_Kni[tid];
        #pragma unroll
        for (int o = 16; o; o >>= 1) v += __shfl_xor_sync(0xffffffffu, v, o);
        if (lane == 0) s_sb[wid] = v * rs;
    }
    __syncthreads();

    // pass 1: sim for local j-half. thread = (jloc, h-half). 384 items exactly.
    {
        int jloc = tid >> 1, hh = tid & 1;
        F4U sb; sb.f = *(const float4*)&s_sb[hh * 4];
        unsigned long long acc2[2] = { sb.u[0], sb.u[1] };
        const float* ep = Es + jloc;
        const float* qp = s_Qk + hh * 4;
        #pragma unroll 8
        for (int e = 0; e < 64; e++) {
            float ev = ep[e * ES_ST];
            unsigned long long evd = pk2(ev, ev);
            F4U q; q.f = *(const float4*)(qp + e * 8);
            acc2[0] = fma2(q.u[0], evd, acc2[0]);
            acc2[1] = fma2(q.u[1], evd, acc2[1]);
        }
        F4U o;
        if (s_mf[jloc] > 0.f) {
            float2 a = upk(acc2[0]), b = upk(acc2[1]);
            o.f = make_float4(a.x, a.y, b.x, b.y);
        } else {
            o.f = make_float4(-INFINITY, -INFINITY, -INFINITY, -INFINITY);
        }
        *(float4*)&s_p[jloc * 12 + hh * 4] = o.f;
    }
    __syncthreads();

    // local softmax stats per head; store raw exp into s_p
    if (wid < 8) {
        int h = wid;
        float m = -INFINITY;
        #pragma unroll
        for (int jl = lane; jl < JH; jl += 32) m = fmaxf(m, s_p[jl * 12 + h]);
        #pragma unroll
        for (int o = 16; o; o >>= 1) m = fmaxf(m, __shfl_xor_sync(0xffffffffu, m, o));
        float mexp = (m == -INFINITY) ? 0.f : m;
        float sum = 0.f;
        #pragma unroll
        for (int jl = lane; jl < JH; jl += 32) {
            float ev = __expf(s_p[jl * 12 + h] - mexp);
            s_p[jl * 12 + h] = ev;
            sum += ev;
        }
        #pragma unroll
        for (int o = 16; o; o >>= 1) sum += __shfl_xor_sync(0xffffffffu, sum, o);
        if (lane == 0) { s_ms[h] = m; s_ms[8 + h] = sum; }
    }
    __syncthreads();
    CLUSTER_SYNC();   // S1: peer's (m, s) visible

    // combine factors per head: fac = exp(m_l - m_g) * maski / total
    if (tid < 8) {
        unsigned base = smem_u32(s_ms);
        unsigned peer = mapa_rank(base, rank ^ 1u);
        float m_l = s_ms[tid],      s_l = s_ms[8 + tid];
        float m_p = ld_dsmem(peer + tid * 4);
        float s_pe = ld_dsmem(peer + (8 + tid) * 4);
        float m_g = fmaxf(m_l, m_p);
        float mg2 = (m_g == -INFINITY) ? 0.f : m_g;
        float tot = s_l * __expf(m_l - mg2) + s_pe * __expf(m_p - mg2);
        s_fac[tid] = __expf(m_l - mg2) * maski / tot;
    }
    __syncthreads();

    // pass 2: partial T over local j, scaled by fac at write
    for (int e = wid; e < 64; e += 12) {
        const float* ep = Es + e * ES_ST;
        unsigned long long acc2[4] = {0ull, 0ull, 0ull, 0ull};
        #pragma unroll
        for (int jl = lane; jl < JH; jl += 32) {
            float ev = ep[jl];
            unsigned long long evd = pk2(ev, ev);
            F4U p0; p0.f = *(const float4*)&s_p[jl * 12];
            F4U p1; p1.f = *(const float4*)&s_p[jl * 12 + 4];
            acc2[0] = fma2(p0.u[0], evd, acc2[0]);
            acc2[1] = fma2(p0.u[1], evd, acc2[1]);
            acc2[2] = fma2(p1.u[0], evd, acc2[2]);
            acc2[3] = fma2(p1.u[1], evd, acc2[3]);
        }
        #pragma unroll
        for (int hp = 0; hp < 4; hp++) {
            float2 v = upk(acc2[hp]);
            #pragma unroll
            for (int o = 16; o; o >>= 1) {
                v.x += __shfl_xor_sync(0xffffffffu, v.x, o);
                v.y += __shfl_xor_sync(0xffffffffu, v.y, o);
            }
            if (lane == 0) {
                s_T[(2 * hp)     * 64 + e] = v.x * s_fac[2 * hp];
                s_T[(2 * hp + 1) * 64 + e] = v.y * s_fac[2 * hp + 1];
            }
        }
    }
    __syncthreads();
    CLUSTER_SYNC();   // S2: peer's scaled partial T visible

    // copy peer T into local buffer
    {
        unsigned tb = smem_u32(s_T);
        unsigned pb = mapa_rank(tb, rank ^ 1u);
        #pragma unroll
        for (int k = tid; k < 512; k += 384) s_Tp[k] = ld_dsmem(pb + k * 4);
    }
    __syncthreads();

    // node_features[hv,i] written by rank 0 only
    if (rank == 0 && tid < 256) {
        int hv = tid, h = hv >> 5;
        const float* wvp = Wv + hv * 192 + 128;
        float acc = s_Vni[hv] * maski;
        #pragma unroll
        for (int e = 0; e < 64; e++)
            acc = fmaf(wvp[e], s_T[h * 64 + e] + s_Tp[h * 64 + e], acc);
        g_nf[hv * N + i] = acc;
    }

    CLUSTER_SYNC();   // S3: don't exit while peer may still read our smem
}

// ============================================================
// Kernel 3: node_out = Wo@nf ; hEo = 0.5*We[:,:256]@nf
// M=192, K=256, cols=384. grid(6,12), 256 thr, tile 32x32.
// ============================================================
__global__ __launch_bounds__(256) void k_post(
    const float* __restrict__ Wo,
    const float* __restrict__ We,
    float* __restrict__ out)
{
    __shared__ float Ws[32][33];
    __shared__ float Ns[32][36];
    int tid = threadIdx.x;
    int r0 = blockIdx.x * 32, n0 = blockIdx.y * 32;
    int co = tid & 31, ro = (tid >> 5) * 4;
    float acc[4] = {0.f, 0.f, 0.f, 0.f};

    for (int k0 = 0; k0 < 256; k0 += 32) {
        {
            int rr = tid >> 3, kl = (tid & 7) * 4;
            int r = r0 + rr;
            const float* wp = (r < 128) ? (Wo + r * 256) : (We + (r - 128) * 320);
            float4 w = *(const float4*)(wp + k0 + kl);
            Ws[rr][kl+0] = w.x; Ws[rr][kl+1] = w.y;
            Ws[rr][kl+2] = w.z; Ws[rr][kl+3] = w.w;
        }
        {
            int kk = tid >> 3, cl = (tid & 7) * 4;
            float4 v = *(const float4*)(g_nf + (k0 + kk) * N + n0 + cl);
            Ns[kk][cl+0] = v.x; Ns[kk][cl+1] = v.y;
            Ns[kk][cl+2] = v.z; Ns[kk][cl+3] = v.w;
        }
        __syncthreads();
        #pragma unroll
        for (int k = 0; k < 32; k++) {
            float ev = Ns[k][co];
            acc[0] = fmaf(Ws[ro+0][k], ev, acc[0]);
            acc[1] = fmaf(Ws[ro+1][k], ev, acc[1]);
            acc[2] = fmaf(Ws[ro+2][k], ev, acc[2]);
            acc[3] = fmaf(Ws[ro+3][k], ev, acc[3]);
        }
        __syncthreads();
    }
    #pragma unroll
    for (int q = 0; q < 4; q++) {
        int r = r0 + ro + q;
        if (r < 128) out[r * N + n0 + co] = acc[q];
        else         g_hEo[(r - 128) * N + n0 + co] = 0.5f * acc[q];
    }
}

// ============================================================
// Kernel 4: edge_out. GEMM [64o,64e] x [64e, 147456c] + rank-1 adds.
// grid(576), 256 thr, 2 CTAs/SM. CTA tile 64o x 256c.
// ============================================================
#define EG_ST 260
#define EDGE_SMEM ((64*68 + 64*EG_ST) * 4)

__global__ __launch_bounds__(256, 2) void k_edge(
    const float* __restrict__ edges,
    const float* __restrict__ We,
    float* __restrict__ out)
{
    extern __shared__ float esm[];
    float* Ws = esm;              // [64][68]  Ws[e][o]
    float* Es = esm + 64 * 68;    // [64][260]

    int tid = threadIdx.x, lane = tid & 31, wid = tid >> 5;
    size_t cbase = (size_t)blockIdx.x * 256;

    {
        int o = tid >> 2, e0 = (tid & 3) * 16;
        const float* wp = We + o * 320 + 256 + e0;
        #pragma unroll
        for (int u = 0; u < 16; u += 4) {
            float4 w = *(const float4*)(wp + u);
            Ws[(e0+u+0)*68 + o] = w.x; Ws[(e0+u+1)*68 + o] = w.y;
            Ws[(e0+u+2)*68 + o] = w.z; Ws[(e0+u+3)*68 + o] = w.w;
        }
    }
    #pragma unroll
    for (int it = 0; it < 16; it++) {
        int idx = it * 256 + tid;
        int e = idx >> 6, c4 = idx & 63;
        float4 v = *(const float4*)(edges + (size_t)e * NN + cbase + c4 * 4);
        *(float4*)&Es[e * EG_ST + c4 * 4] = v;
    }
    __syncthreads();

    int o0 = wid * 8;
    int cl = lane * 4;

    unsigned long long acc2[4][8];
    #pragma unroll
    for (int op = 0; op < 4; op++)
        #pragma unroll
        for (int p = 0; p < 8; p++) acc2[op][p] = 0ull;

    #pragma unroll 4
    for (int e = 0; e < 64; e++) {
        const float* wr = Ws + e * 68 + o0;
        F4U w0; w0.f = *(const float4*)wr;
        F4U w1; w1.f = *(const float4*)(wr + 4);
        unsigned long long wd[4] = { w0.u[0], w0.u[1], w1.u[0], w1.u[1] };
        const float* er = Es + e * EG_ST + cl;
        float4 ea = *(const float4*)er;
        float4 eb = *(const float4*)(er + 128);
        float ev[8] = { ea.x, ea.y, ea.z, ea.w, eb.x, eb.y, eb.z, eb.w };
        #pragma unroll
        for (int p = 0; p < 8; p++) {
            unsigned long long evd = pk2(ev[p], ev[p]);
            acc2[0][p] = fma2(wd[0], evd, acc2[0][p]);
            acc2[1][p] = fma2(wd[1], evd, acc2[1][p]);
            acc2[2][p] = fma2(wd[2], evd, acc2[2][p]);
            acc2[3][p] = fma2(wd[3], evd, acc2[3][p]);
        }
    }

    float* ob = out + 128 * N;
    #pragma unroll
    for (int s = 0; s < 2; s++) {
        size_t c = cbase + cl + s * 128;
        int ii = (int)(c / 384), jj = (int)(c % 384);
        #pragma unroll
        for (int op = 0; op < 4; op++) {
            int oA = o0 + 2 * op, oB = oA + 1;
            float eoiA = g_hEo[oA * N + ii];
            float eoiB = g_hEo[oB * N + ii];
            float4 ejA = *(const float4*)(g_hEo + oA * N + jj);
            float4 ejB = *(const float4*)(g_hEo + oB * N + jj);
            float2 v0 = upk(acc2[op][s*4+0]);
            float2 v1 = upk(acc2[op][s*4+1]);
            float2 v2 = upk(acc2[op][s*4+2]);
            float2 v3 = upk(acc2[op][s*4+3]);
            float* pA = ob + (size_t)oA * NN + c;
            float* pB = ob + (size_t)oB * NN + c;
            *(float4*)pA = make_float4(v0.x + eoiA + ejA.x, v1.x + eoiA + ejA.y,
                                       v2.x + eoiA + ejA.z, v3.x + eoiA + ejA.w);
            *(float4*)pB = make_float4(v0.y + eoiB + ejB.x, v1.y + eoiB + ejB.y,
                                       v2.y + eoiB + ejB.z, v3.y + eoiB + ejB.w);
        }
    }
}

// ============================================================
extern "C" void kernel_launch(void* const* d_in, const int* in_sizes, int n_in,
                              void* d_out, int out_size)
{
    const float* nodes = (const float*)d_in[0];
    const float* edges = (const float*)d_in[1];
    const unsigned int* mask = (const unsigned int*)d_in[2];
    const float* Wq = (const float*)d_in[3];
    const float* Wk = (const float*)d_in[4];
    const float* Wv = (const float*)d_in[5];
    const float* Wo = (const float*)d_in[6];
    const float* We = (const float*)d_in[7];
    float* out = (float*)d_out;

    cudaFuncSetAttribute(k_attn, cudaFuncAttributeMaxDynamicSharedMemorySize, ATTN_SMEM);
    cudaFuncSetAttribute(k_edge, cudaFuncAttributeMaxDynamicSharedMemorySize, EDGE_SMEM);

    k_prep<<<dim3(24, 12), 256>>>(nodes, Wq, Wk, Wv, mask);
    k_attn<<<768, 384, ATTN_SMEM>>>(edges, Wk, Wv);
    k_post<<<dim3(6, 12), 256>>>(Wo, We, out);
    k_edge<<<576, 256, EDGE_SMEM>>>(edges, We, out);
}

// round 7
// speedup vs baseline: 1.5178x; 1.5178x over previous
#include <cuda_runtime.h>
#include <math.h>

#define N   384
#define NN  (384*384)
#define JQ  96
#define EA_ST 100

// ---- scratch (device globals; no allocation allowed) ----
__device__ float g_q   [256*N];
__device__ float g_Kn  [256*N];
__device__ float g_Vn  [256*N];
__device__ float g_nf  [256*N];
__device__ float g_hEo [64*N];
__device__ float g_mask[N];
__device__ float g_part[384*4*528];   // per (i, quarter): m[8], s[8], T[8][64]

// ---- packed f32x2 helpers (Blackwell FFMA2) ----
__device__ __forceinline__ unsigned long long pk2(float a, float b) {
    unsigned long long d;
    asm("mov.b64 %0, {%1, %2};" : "=l"(d) : "f"(a), "f"(b));
    return d;
}
__device__ __forceinline__ unsigned long long fma2(unsigned long long a,
                                                   unsigned long long b,
                                                   unsigned long long c) {
    unsigned long long d;
    asm("fma.rn.f32x2 %0, %1, %2, %3;" : "=l"(d) : "l"(a), "l"(b), "l"(c));
    return d;
}
__device__ __forceinline__ float2 upk(unsigned long long v) {
    float2 r;
    asm("mov.b64 {%0, %1}, %2;" : "=f"(r.x), "=f"(r.y) : "l"(v));
    return r;
}
union F4U { float4 f; unsigned long long u[2]; };

// ============================================================
// Kernel 1: fused GEMM q|Kn|Vn. M=768, K=128, cols=384.
// grid(24,12), 256 thr, tile 32x32. Block(0,0) decodes mask.
// ============================================================
__global__ __launch_bounds__(256) void k_prep(
    const float* __restrict__ nodes,
    const float* __restrict__ Wq,
    const float* __restrict__ Wk,
    const float* __restrict__ Wv,
    const unsigned int* __restrict__ maskw)
{
    __shared__ float Ws[32][33];
    __shared__ float Ns[32][36];
    __shared__ int s_flagF, s_flagB;
    int tid = threadIdx.x;

    if (blockIdx.x == 0 && blockIdx.y == 0) {
        if (tid == 0) { s_flagF = 0; s_flagB = 0; }
        __syncthreads();
        if (tid < 96) {
            unsigned v = maskw[tid];
            if (v == 0x3f800000u) atomicOr(&s_flagF, 1);   // float32 1.0
            else if (v > 1u)      atomicOr(&s_flagB, 1);   // packed u8
        }
        __syncthreads();
        bool byte_mode = (!s_flagF) && s_flagB;
        for (int j = tid; j < N; j += 256) {
            float val;
            if (byte_mode) {
                unsigned w = maskw[j >> 2];
                val = ((w >> ((j & 3) * 8)) & 0xffu) ? 1.0f : 0.0f;
            } else {
                val = maskw[j] ? 1.0f : 0.0f;   // int32 or f32 bits
            }
            g_mask[j] = val;
        }
    }

    int r0 = blockIdx.x * 32, n0 = blockIdx.y * 32;
    int co = tid & 31, ro = (tid >> 5) * 4;
    float acc[4] = {0.f, 0.f, 0.f, 0.f};

    for (int k0 = 0; k0 < 128; k0 += 32) {
        {
            int rr = tid >> 3, kl = (tid & 7) * 4;
            int r = r0 + rr;
            const float* wp;
            if      (r < 256) wp = Wq + r * 128;
            else if (r < 512) wp = Wk + (r - 256) * 192;
            else              wp = Wv + (r - 512) * 192;
            float4 w = *(const float4*)(wp + k0 + kl);
            Ws[rr][kl+0] = w.x; Ws[rr][kl+1] = w.y;
            Ws[rr][kl+2] = w.z; Ws[rr][kl+3] = w.w;
        }
        {
            int kk = tid >> 3, cl = (tid & 7) * 4;
            float4 v = *(const float4*)(nodes + (k0 + kk) * N + n0 + cl);
            Ns[kk][cl+0] = v.x; Ns[kk][cl+1] = v.y;
            Ns[kk][cl+2] = v.z; Ns[kk][cl+3] = v.w;
        }
        __syncthreads();
        #pragma unroll
        for (int k = 0; k < 32; k++) {
            float ev = Ns[k][co];
            acc[0] = fmaf(Ws[ro+0][k], ev, acc[0]);
            acc[1] = fmaf(Ws[ro+1][k], ev, acc[1]);
            acc[2] = fmaf(Ws[ro+2][k], ev, acc[2]);
            acc[3] = fmaf(Ws[ro+3][k], ev, acc[3]);
        }
        __syncthreads();
    }
    #pragma unroll
    for (int q = 0; q < 4; q++) {
        int r = r0 + ro + q;
        float* op;
        if      (r < 256) op = g_q  + r * N;
        else if (r < 512) op = g_Kn + (r - 256) * N;
        else              op = g_Vn + (r - 512) * N;
        op[n0 + co] = acc[q];
    }
}

// ============================================================
// Kernel 2a: attention partials. grid(1536) = 384 i x 4 quarters.
// 256 thr, ~37KB static smem (6 CTAs/SM). Writes m/s/raw-T to g_part.
// ============================================================
__global__ __launch_bounds__(256) void k_attnA(
    const float* __restrict__ edges,
    const float* __restrict__ Wk)
{
    __shared__ float Es[64 * EA_ST];
    __shared__ float s_p[JQ * 12];
    __shared__ float s_qi[256], s_Kni[256];
    __shared__ float s_Qk[512];
    __shared__ float s_T[512];
    __shared__ float s_ms[16];
    __shared__ float s_sb[8];
    __shared__ float s_mf[JQ];

    int bx = blockIdx.x;
    int i = bx >> 2, qn = bx & 3, jb = qn * JQ;
    int tid = threadIdx.x, lane = tid & 31, wid = tid >> 5;

    s_qi [tid] = g_q [tid * N + i];
    s_Kni[tid] = g_Kn[tid * N + i];
    if (tid < JQ) s_mf[tid] = g_mask[jb + tid];

    // stage edges[e, i, jb..jb+95]: 64 x 24 float4 = 1536 / 256 = 6 each
    const float* erow = edges + (size_t)i * N + jb;
    #pragma unroll
    for (int it = 0; it < 6; it++) {
        int idx = it * 256 + tid;
        int e = idx / 24, c4 = idx - e * 24;
        float4 v = *(const float4*)(erow + (size_t)e * NN + c4 * 4);
        *(float4*)&Es[e * EA_ST + c4 * 4] = v;
    }
    __syncthreads();

    const float rs = 0.17677669529663687f;  // 1/sqrt(32)

    // Qk[e][h] = rs * sum_a q[h*32+a] * Wk[h*32+a][128+e]  (512 items)
    {
        int idx = tid;
        #pragma unroll
        for (int rep = 0; rep < 2; rep++) {
            int h = idx >> 6, e = idx & 63;
            const float* wkp = Wk + (h * 32) * 192 + 128 + e;
            float acc = 0.f;
            #pragma unroll
            for (int a = 0; a < 32; a++) acc = fmaf(s_qi[h * 32 + a], wkp[a * 192], acc);
            s_Qk[e * 8 + h] = acc * rs;
            idx += 256;
        }
    }
    {   // sim_base[h], warps 0..7
        float v = s_qi[tid] * s_Kni[tid];
        #pragma unroll
        for (int o = 16; o; o >>= 1) v += __shfl_xor_sync(0xffffffffu, v, o);
        if (lane == 0) s_sb[wid] = v * rs;
    }
    __syncthreads();

    // pass 1: sim for local quarter. thread = (jloc, h-half). 192 items.
    if (tid < 2 * JQ) {
        int jloc = tid >> 1, hh = tid & 1;
        F4U sb; sb.f = *(const float4*)&s_sb[hh * 4];
        unsigned long long acc2[2] = { sb.u[0], sb.u[1] };
        const float* ep = Es + jloc;
        const float* qp = s_Qk + hh * 4;
        #pragma unroll 8
        for (int e = 0; e < 64; e++) {
            float ev = ep[e * EA_ST];
            unsigned long long evd = pk2(ev, ev);
            F4U q; q.f = *(const float4*)(qp + e * 8);
            acc2[0] = fma2(q.u[0], evd, acc2[0]);
            acc2[1] = fma2(q.u[1], evd, acc2[1]);
        }
        F4U o;
        if (s_mf[jloc] > 0.f) {
            float2 a = upk(acc2[0]), b = upk(acc2[1]);
            o.f = make_float4(a.x, a.y, b.x, b.y);
        } else {
            o.f = make_float4(-INFINITY, -INFINITY, -INFINITY, -INFINITY);
        }
        *(float4*)&s_p[jloc * 12 + hh * 4] = o.f;
    }
    __syncthreads();

    // local softmax stats per head; s_p <- raw exp(sim - m_local)
    if (wid < 8) {
        int h = wid;
        float m = -INFINITY;
        #pragma unroll
        for (int jl = lane; jl < JQ; jl += 32) m = fmaxf(m, s_p[jl * 12 + h]);
        #pragma unroll
        for (int o = 16; o; o >>= 1) m = fmaxf(m, __shfl_xor_sync(0xffffffffu, m, o));
        float mexp = (m == -INFINITY) ? 0.f : m;
        float sum = 0.f;
        #pragma unroll
        for (int jl = lane; jl < JQ; jl += 32) {
            float ev = __expf(s_p[jl * 12 + h] - mexp);
            s_p[jl * 12 + h] = ev;
            sum += ev;
        }
        #pragma unroll
        for (int o = 16; o; o >>= 1) sum += __shfl_xor_sync(0xffffffffu, sum, o);
        if (lane == 0) { s_ms[h] = m; s_ms[8 + h] = sum; }
    }
    __syncthreads();

    // raw partial T over local quarter
    #pragma unroll 1
    for (int k = 0; k < 8; k++) {
        int e = wid + k * 8;
        const float* ep = Es + e * EA_ST;
        unsigned long long acc2[4] = {0ull, 0ull, 0ull, 0ull};
        #pragma unroll
        for (int jl = lane; jl < JQ; jl += 32) {
            float ev = ep[jl];
            unsigned long long evd = pk2(ev, ev);
            F4U p0; p0.f = *(const float4*)&s_p[jl * 12];
            F4U p1; p1.f = *(const float4*)&s_p[jl * 12 + 4];
            acc2[0] = fma2(p0.u[0], evd, acc2[0]);
            acc2[1] = fma2(p0.u[1], evd, acc2[1]);
            acc2[2] = fma2(p1.u[0], evd, acc2[2]);
            acc2[3] = fma2(p1.u[1], evd, acc2[3]);
        }
        #pragma unroll
        for (int hp = 0; hp < 4; hp++) {
            float2 v = upk(acc2[hp]);
            #pragma unroll
            for (int o = 16; o; o >>= 1) {
                v.x += __shfl_xor_sync(0xffffffffu, v.x, o);
                v.y += __shfl_xor_sync(0xffffffffu, v.y, o);
            }
            if (lane == 0) {
                s_T[(2 * hp)     * 64 + e] = v.x;
                s_T[(2 * hp + 1) * 64 + e] = v.y;
            }
        }
    }
    __syncthreads();

    // coalesced dump: [m8 | s8 | T512]
    float* gp = g_part + ((size_t)i * 4 + qn) * 528;
    if (tid < 16) gp[tid] = s_ms[tid];
    #pragma unroll
    for (int r = 0; r < 2; r++) {
        int idx = r * 256 + tid;
        gp[16 + idx] = s_T[idx];
    }
}

// ============================================================
// Kernel 2b: combine quarters -> node_features. grid(384), 256 thr.
// ============================================================
__global__ __launch_bounds__(256) void k_attnB(const float* __restrict__ Wv)
{
    __shared__ float s_T[512];
    __shared__ float s_fac[32];
    int i = blockIdx.x;
    int tid = threadIdx.x;
    float maski = g_mask[i];
    const float* gp = g_part + (size_t)i * 4 * 528;

    if (tid < 32) {
        int q = tid >> 3, h = tid & 7;
        float m = gp[q * 528 + h];
        float s = gp[q * 528 + 8 + h];
        float mg = m;
        mg = fmaxf(mg, __shfl_xor_sync(0xffffffffu, mg, 8));
        mg = fmaxf(mg, __shfl_xor_sync(0xffffffffu, mg, 16));
        float mg2 = (mg == -INFINITY) ? 0.f : mg;
        float w = s * __expf(m - mg2);
        float tot = w;
        tot += __shfl_xor_sync(0xffffffffu, tot, 8);
        tot += __shfl_xor_sync(0xffffffffu, tot, 16);
        s_fac[q * 8 + h] = __expf(m - mg2) * maski / tot;
    }
    __syncthreads();

    #pragma unroll
    for (int r = 0; r < 2; r++) {
        int idx = r * 256 + tid;
        int h = idx >> 6;
        float acc = 0.f;
        #pragma unroll
        for (int q = 0; q < 4; q++)
            acc = fmaf(s_fac[q * 8 + h], gp[q * 528 + 16 + idx], acc);
        s_T[idx] = acc;
    }
    __syncthreads();

    {
        int hv = tid, h = hv >> 5;
        const float* wvp = Wv + hv * 192 + 128;
        float acc = g_Vn[hv * N + i] * maski;
        #pragma unroll
        for (int e = 0; e < 64; e++) acc = fmaf(wvp[e], s_T[h * 64 + e], acc);
        g_nf[hv * N + i] = acc;
    }
}

// ============================================================
// Kernel 3: node_out = Wo@nf ; hEo = 0.5*We[:,:256]@nf
// M=192, K=256, cols=384. grid(6,12), 256 thr, tile 32x32.
// ============================================================
__global__ __launch_bounds__(256) void k_post(
    const float* __restrict__ Wo,
    const float* __restrict__ We,
    float* __restrict__ out)
{
    __shared__ float Ws[32][33];
    __shared__ float Ns[32][36];
    int tid = threadIdx.x;
    int r0 = blockIdx.x * 32, n0 = blockIdx.y * 32;
    int co = tid & 31, ro = (tid >> 5) * 4;
    float acc[4] = {0.f, 0.f, 0.f, 0.f};

    for (int k0 = 0; k0 < 256; k0 += 32) {
        {
            int rr = tid >> 3, kl = (tid & 7) * 4;
            int r = r0 + rr;
            const float* wp = (r < 128) ? (Wo + r * 256) : (We + (r - 128) * 320);
            float4 w = *(const float4*)(wp + k0 + kl);
            Ws[rr][kl+0] = w.x; Ws[rr][kl+1] = w.y;
            Ws[rr][kl+2] = w.z; Ws[rr][kl+3] = w.w;
        }
        {
            int kk = tid >> 3, cl = (tid & 7) * 4;
            float4 v = *(const float4*)(g_nf + (k0 + kk) * N + n0 + cl);
            Ns[kk][cl+0] = v.x; Ns[kk][cl+1] = v.y;
            Ns[kk][cl+2] = v.z; Ns[kk][cl+3] = v.w;
        }
        __syncthreads();
        #pragma unroll
        for (int k = 0; k < 32; k++) {
            float ev = Ns[k][co];
            acc[0] = fmaf(Ws[ro+0][k], ev, acc[0]);
            acc[1] = fmaf(Ws[ro+1][k], ev, acc[1]);
            acc[2] = fmaf(Ws[ro+2][k], ev, acc[2]);
            acc[3] = fmaf(Ws[ro+3][k], ev, acc[3]);
        }
        __syncthreads();
    }
    #pragma unroll
    for (int q = 0; q < 4; q++) {
        int r = r0 + ro + q;
        if (r < 128) out[r * N + n0 + co] = acc[q];
        else         g_hEo[(r - 128) * N + n0 + co] = 0.5f * acc[q];
    }
}

// ============================================================
// Kernel 4: edge_out. GEMM [64o,64e] x [64e, 147456c] + rank-1 adds.
// grid(576), 256 thr, 2 CTAs/SM. CTA tile 64o x 256c.
// ============================================================
#define EG_ST 260
#define EDGE_SMEM ((64*68 + 64*EG_ST) * 4)

__global__ __launch_bounds__(256, 2) void k_edge(
    const float* __restrict__ edges,
    const float* __restrict__ We,
    float* __restrict__ out)
{
    extern __shared__ float esm[];
    float* Ws = esm;              // [64][68]  Ws[e][o]
    float* Es = esm + 64 * 68;    // [64][260]

    int tid = threadIdx.x, lane = tid & 31, wid = tid >> 5;
    size_t cbase = (size_t)blockIdx.x * 256;

    {
        int o = tid >> 2, e0 = (tid & 3) * 16;
        const float* wp = We + o * 320 + 256 + e0;
        #pragma unroll
        for (int u = 0; u < 16; u += 4) {
            float4 w = *(const float4*)(wp + u);
            Ws[(e0+u+0)*68 + o] = w.x; Ws[(e0+u+1)*68 + o] = w.y;
            Ws[(e0+u+2)*68 + o] = w.z; Ws[(e0+u+3)*68 + o] = w.w;
        }
    }
    #pragma unroll
    for (int it = 0; it < 16; it++) {
        int idx = it * 256 + tid;
        int e = idx >> 6, c4 = idx & 63;
        float4 v = *(const float4*)(edges + (size_t)e * NN + cbase + c4 * 4);
        *(float4*)&Es[e * EG_ST + c4 * 4] = v;
    }
    __syncthreads();

    int o0 = wid * 8;
    int cl = lane * 4;

    unsigned long long acc2[4][8];
    #pragma unroll
    for (int op = 0; op < 4; op++)
        #pragma unroll
        for (int p = 0; p < 8; p++) acc2[op][p] = 0ull;

    #pragma unroll 4
    for (int e = 0; e < 64; e++) {
        const float* wr = Ws + e * 68 + o0;
        F4U w0; w0.f = *(const float4*)wr;
        F4U w1; w1.f = *(const float4*)(wr + 4);
        unsigned long long wd[4] = { w0.u[0], w0.u[1], w1.u[0], w1.u[1] };
        const float* er = Es + e * EG_ST + cl;
        float4 ea = *(const float4*)er;
        float4 eb = *(const float4*)(er + 128);
        float ev[8] = { ea.x, ea.y, ea.z, ea.w, eb.x, eb.y, eb.z, eb.w };
        #pragma unroll
        for (int p = 0; p < 8; p++) {
            unsigned long long evd = pk2(ev[p], ev[p]);
            acc2[0][p] = fma2(wd[0], evd, acc2[0][p]);
            acc2[1][p] = fma2(wd[1], evd, acc2[1][p]);
            acc2[2][p] = fma2(wd[2], evd, acc2[2][p]);
            acc2[3][p] = fma2(wd[3], evd, acc2[3][p]);
        }
    }

    float* ob = out + 128 * N;
    #pragma unroll
    for (int s = 0; s < 2; s++) {
        size_t c = cbase + cl + s * 128;
        int ii = (int)(c / 384), jj = (int)(c % 384);
        #pragma unroll
        for (int op = 0; op < 4; op++) {
            int oA = o0 + 2 * op, oB = oA + 1;
            float eoiA = g_hEo[oA * N + ii];
            float eoiB = g_hEo[oB * N + ii];
            float4 ejA = *(const float4*)(g_hEo + oA * N + jj);
            float4 ejB = *(const float4*)(g_hEo + oB * N + jj);
            float2 v0 = upk(acc2[op][s*4+0]);
            float2 v1 = upk(acc2[op][s*4+1]);
            float2 v2 = upk(acc2[op][s*4+2]);
            float2 v3 = upk(acc2[op][s*4+3]);
            float* pA = ob + (size_t)oA * NN + c;
            float* pB = ob + (size_t)oB * NN + c;
            *(float4*)pA = make_float4(v0.x + eoiA + ejA.x, v1.x + eoiA + ejA.y,
                                       v2.x + eoiA + ejA.z, v3.x + eoiA + ejA.w);
            *(float4*)pB = make_float4(v0.y + eoiB + ejB.x, v1.y + eoiB + ejB.y,
                                       v2.y + eoiB + ejB.z, v3.y + eoiB + ejB.w);
        }
    }
}

// ============================================================
extern "C" void kernel_launch(void* const* d_in, const int* in_sizes, int n_in,
                              void* d_out, int out_size)
{
    const float* nodes = (const float*)d_in[0];
    const float* edges = (const float*)d_in[1];
    const unsigned int* mask = (const unsigned int*)d_in[2];
    const float* Wq = (const float*)d_in[3];
    const float* Wk = (const float*)d_in[4];
    const float* Wv = (const float*)d_in[5];
    const float* Wo = (const float*)d_in[6];
    const float* We = (const float*)d_in[7];
    float* out = (float*)d_out;

    cudaFuncSetAttribute(k_edge, cudaFuncAttributeMaxDynamicSharedMemorySize, EDGE_SMEM);

    k_prep<<<dim3(24, 12), 256>>>(nodes, Wq, Wk, Wv, mask);
    k_attnA<<<1536, 256>>>(edges, Wk);
    k_attnB<<<384, 256>>>(Wv);
    k_post<<<dim3(6, 12), 256>>>(Wo, We, out);
    k_edge<<<576, 256, EDGE_SMEM>>>(edges, We, out);
}